// round 15
// baseline (speedup 1.0000x reference)
#include <cuda_runtime.h>
#include <cuda_bf16.h>
#include <cstdint>

#define D 64
#define MAX_TOKENS 4096

// Scratch (no cudaMalloc allowed)
__device__ __align__(16) __nv_bfloat16 g_hi[MAX_TOKENS * D];
__device__ float g_P[MAX_TOKENS];   // 2 / (1 - x2)
__device__ float g_U[MAX_TOKENS];   // x2 / (1 - x2)

// ---------------------------------------------------------------------------
// helpers
// ---------------------------------------------------------------------------
__device__ __forceinline__ uint32_t smem_u32(const void* p) {
    uint32_t a;
    asm("{ .reg .u64 t; cvta.to.shared.u64 t, %1; cvt.u32.u64 %0, t; }"
        : "=r"(a) : "l"(p));
    return a;
}
__device__ __forceinline__ void cp_async16(uint32_t dst, const void* src) {
    asm volatile("cp.async.cg.shared.global [%0], [%1], 16;"
                 :: "r"(dst), "l"(src) : "memory");
}
__device__ __forceinline__ void cp_commit() {
    asm volatile("cp.async.commit_group;" ::: "memory");
}
template <int N>
__device__ __forceinline__ void cp_wait() {
    asm volatile("cp.async.wait_group %0;" :: "n"(N) : "memory");
}
__device__ __forceinline__ void ldsm_x4(uint32_t& r0, uint32_t& r1,
                                        uint32_t& r2, uint32_t& r3,
                                        uint32_t addr) {
    asm volatile("ldmatrix.sync.aligned.m8n8.x4.shared.b16 {%0,%1,%2,%3}, [%4];"
                 : "=r"(r0), "=r"(r1), "=r"(r2), "=r"(r3) : "r"(addr));
}
__device__ __forceinline__ void mma16816(float* d, const uint32_t* a,
                                         const uint32_t* b) {
    asm volatile(
        "mma.sync.aligned.m16n8k16.row.col.f32.bf16.bf16.f32 "
        "{%0,%1,%2,%3}, {%4,%5,%6,%7}, {%8,%9}, {%0,%1,%2,%3};"
        : "+f"(d[0]), "+f"(d[1]), "+f"(d[2]), "+f"(d[3])
        : "r"(a[0]), "r"(a[1]), "r"(a[2]), "r"(a[3]), "r"(b[0]), "r"(b[1]));
}

// ---------------------------------------------------------------------------
// Prep: 4 tokens per warp (8 lanes each). id-dtype detect, gather, project,
// P/U, bf16 store. Signals dependent (bias) grid via PDL when done.
// ---------------------------------------------------------------------------
__global__ __launch_bounds__(256)
void prep_kernel(const void* __restrict__ ids_raw,
                 const float* __restrict__ W,
                 int n_ids, int num_tok) {
    const int* w32 = (const int*)ids_raw;
    int any = 0;
    int nscan = n_ids < 1024 ? n_ids : 1024;
    for (int i = threadIdx.x * 2 + 1; i < nscan; i += 512) any |= w32[i];
    int is64 = (__syncthreads_or(any) == 0);

    int gw = (blockIdx.x * blockDim.x + threadIdx.x) >> 5;
    int lane = threadIdx.x & 31;
    int sub = lane >> 3, l8 = lane & 7;
    int tok = gw * 4 + sub;

    if (tok < n_ids) {
        long long id = is64 ? ((const long long*)ids_raw)[tok]
                            : (long long)w32[tok];
        if (id < 0) id = 0;
        if (id > (long long)(num_tok - 1)) id = num_tok - 1;

        const float4* w4 = (const float4*)(W + (size_t)id * D);
        float4 va = w4[l8 * 2];
        float4 vb = w4[l8 * 2 + 1];
        float s = va.x * va.x + va.y * va.y + va.z * va.z + va.w * va.w
                + vb.x * vb.x + vb.y * vb.y + vb.z * vb.z + vb.w * vb.w;
#pragma unroll
        for (int o = 4; o; o >>= 1) s += __shfl_xor_sync(0xffffffffu, s, o);

        const float max_norm = 1.0f - 1e-5f;
        float norm = sqrtf(s);
        float f = (norm > max_norm) ? (max_norm / fmaxf(norm, 1e-12f)) : 1.0f;
        float s2 = s * f * f;

        __nv_bfloat162 p0, p1, p2, p3;
        p0.x = __float2bfloat16_rn(va.x * f); p0.y = __float2bfloat16_rn(va.y * f);
        p1.x = __float2bfloat16_rn(va.z * f); p1.y = __float2bfloat16_rn(va.w * f);
        p2.x = __float2bfloat16_rn(vb.x * f); p2.y = __float2bfloat16_rn(vb.y * f);
        p3.x = __float2bfloat16_rn(vb.z * f); p3.y = __float2bfloat16_rn(vb.w * f);
        uint4 h;
        h.x = *(uint32_t*)&p0; h.y = *(uint32_t*)&p1;
        h.z = *(uint32_t*)&p2; h.w = *(uint32_t*)&p3;
        ((uint4*)(g_hi + (size_t)tok * D))[l8] = h;

        if (l8 == 0) {
            float r = 1.0f / (1.0f - s2);
            g_P[tok] = 2.0f * r;
            g_U[tok] = s2 * r;
        }
    }
    __threadfence();
    asm volatile("griddepcontrol.launch_dependents;");
}

// ---------------------------------------------------------------------------
// Epilogue element: x = Pi*Uj + Pj*Ui - Pi*Pj*g ; dist = acosh(1+x).
// ---------------------------------------------------------------------------
__device__ __forceinline__ float bias_elt(float Pi, float Ui, float Pj,
                                          float Uj, float g, float nscln2) {
    float m  = Pj * Ui;
    float f1 = fmaf(Pi, Uj, m);
    float tt = Pi * Pj;
    float x  = fmaf(-tt, g, f1);
    float xe = fmaxf(x, 1.1920929e-7f);          // matches ref clamp (1+1e-7)
    float pr = fmaf(xe, xe, xe + xe);            // xe*(xe+2)
    float s;
    asm("sqrt.approx.f32 %0, %1;" : "=f"(s) : "f"(pr));
    float y = 1.0f + (xe + s);
    float l;
    asm("lg2.approx.f32 %0, %1;" : "=f"(l) : "f"(y));
    return nscln2 * l;                            // -sc * ln(y)
}
__device__ __forceinline__ float bias_elt_d(float Pi, float Ui, float Pj,
                                            float Uj, float g, float nscln2,
                                            bool force) {
    float m  = Pj * Ui;
    float f1 = fmaf(Pi, Uj, m);
    float tt = Pi * Pj;
    float x  = fmaf(-tt, g, f1);
    x = force ? 0.0f : x;
    float xe = fmaxf(x, 1.1920929e-7f);
    float pr = fmaf(xe, xe, xe + xe);
    float s;
    asm("sqrt.approx.f32 %0, %1;" : "=f"(s) : "f"(pr));
    float y = 1.0f + (xe + s);
    float l;
    asm("lg2.approx.f32 %0, %1;" : "=f"(l) : "f"(y));
    return nscln2 * l;
}

// ---------------------------------------------------------------------------
// Layout: two full tile buffers for cp.async double buffering.
// ---------------------------------------------------------------------------
#define LDB     144                     // bytes per smem bf16 tile row
#define T_A     0                       // i-block (within buffer)
#define T_B     (64 * LDB)              // j-block
#define O_PU    (2 * 64 * LDB)          // P/U block: PI,UI,PJ,UJ x 256B each
#define BUF     (O_PU + 1024)           // 19456 bytes per buffer
#define SMEM_TOT (2 * BUF)              // 38912 bytes
#define PSTAG   68                      // f32 staging pitch (floats)

// decode linear upper-triangle index -> (b, ti, tj)
__device__ __forceinline__ void decode_tile(int idx, int ntile, int npairs,
                                            int& b, int& ti, int& tj) {
    b = idx / npairs;
    int p = idx - b * npairs;
    int rev = npairs - 1 - p;
    float frf = sqrtf(8.0f * (float)rev + 1.0f);
    int r = (int)((frf - 1.0f) * 0.5f);
    while ((r + 1) * (r + 2) / 2 <= rev) r++;
    while (r * (r + 1) / 2 > rev) r--;
    int c = rev - r * (r + 1) / 2;
    ti = ntile - 1 - r;
    tj = ntile - 1 - c;
}

// stage one tile pair (i-block + j-block + P/U) into buffer via cp.async
__device__ __forceinline__ void stage_tile(uint32_t sb, int bufOff,
                                           int base, int i0, int j0, int t) {
    const uint4* srcA = (const uint4*)(g_hi + (size_t)(base + i0) * D);
    const uint4* srcB = (const uint4*)(g_hi + (size_t)(base + j0) * D);
#pragma unroll
    for (int it = 0; it < 2; it++) {
        int idx2 = t + it * 256;            // 0..511
        int row2 = idx2 >> 3, ch = idx2 & 7;
        cp_async16(sb + bufOff + T_A + row2 * LDB + ch * 16, srcA + row2 * 8 + ch);
        cp_async16(sb + bufOff + T_B + row2 * LDB + ch * 16, srcB + row2 * 8 + ch);
    }
    if (t < 64) {
        int arr = t >> 4, ch = t & 15;      // 4 arrays x 16 chunks of 16B
        const float* s4 = (arr == 0) ? g_P + base + i0
                        : (arr == 1) ? g_U + base + i0
                        : (arr == 2) ? g_P + base + j0
                                     : g_U + base + j0;
        cp_async16(sb + bufOff + O_PU + arr * 256 + ch * 16, s4 + ch * 4);
    }
    cp_commit();
}

// full per-tile compute: mainloop + epilogue (+ mirror)
__device__ __forceinline__ void process_tile(char* sm, uint32_t sb, int bufOff,
                                             int b, int ti, int tj,
                                             float* __restrict__ out, int S,
                                             float nscln2, int t, int wid,
                                             int lane) {
    bool mirror = (ti != tj);
    int i0 = ti * 64, j0 = tj * 64;

    int wm = wid >> 2;          // 0..1  (m block of 32)
    int wn = wid & 3;           // 0..3  (n block of 16)

    float acc[2][2][4];
#pragma unroll
    for (int mt = 0; mt < 2; mt++)
#pragma unroll
        for (int nt = 0; nt < 2; nt++)
#pragma unroll
            for (int r2 = 0; r2 < 4; r2++) acc[mt][nt][r2] = 0.0f;

    int lm = lane >> 3, lr = lane & 7;
    int a_row = wm * 32 + (lm & 1) * 8 + lr;
    int a_kb  = (lm >> 1) * 16;
    int b_row = wn * 16 + ((lane >> 4) & 1) * 8 + lr;
    int b_kb  = ((lane >> 3) & 1) * 16;

    uint32_t aBase = sb + bufOff + T_A + a_row * LDB + a_kb;
    uint32_t bBase = sb + bufOff + T_B + b_row * LDB + b_kb;

#pragma unroll
    for (int ks = 0; ks < 4; ks++) {
        uint32_t a[2][4], bf[2][2];
        ldsm_x4(a[0][0], a[0][1], a[0][2], a[0][3], aBase + ks * 32);
        ldsm_x4(a[1][0], a[1][1], a[1][2], a[1][3],
                aBase + 16 * LDB + ks * 32);
        ldsm_x4(bf[0][0], bf[0][1], bf[1][0], bf[1][1], bBase + ks * 32);
        mma16816(acc[0][0], a[0], bf[0]);
        mma16816(acc[0][1], a[0], bf[1]);
        mma16816(acc[1][0], a[1], bf[0]);
        mma16816(acc[1][1], a[1], bf[1]);
    }

    // All ldsm reads done; staging may overwrite the tile region of THIS buf.
    __syncthreads();

    int g  = lane >> 2;          // 0..7
    int tq = lane & 3;           // 0..3
    const float* sPi = (const float*)(sm + bufOff + O_PU);
    const float* sUi = (const float*)(sm + bufOff + O_PU + 256);
    const float* sPj = (const float*)(sm + bufOff + O_PU + 512);
    const float* sUj = (const float*)(sm + bufOff + O_PU + 768);
    float* stag = (float*)(sm + bufOff);   // [j][i], overlays this buf's tiles

    if (mirror) {
#pragma unroll
        for (int mt = 0; mt < 2; mt++) {
            int i_a = wm * 32 + mt * 16 + g;
            int i_b = i_a + 8;
            float Pia = sPi[i_a], Uia = sUi[i_a];
            float Pib = sPi[i_b], Uib = sUi[i_b];
            size_t rowA = (size_t)b * S * S + (size_t)(i0 + i_a) * S + j0;
            size_t rowB = rowA + 8u * S;
#pragma unroll
            for (int nt = 0; nt < 2; nt++) {
                int j_c = wn * 16 + nt * 8 + 2 * tq;
                float Pj0 = sPj[j_c],     Uj0 = sUj[j_c];
                float Pj1 = sPj[j_c + 1], Uj1 = sUj[j_c + 1];
                float2 oA, oB;
                oA.x = bias_elt(Pia, Uia, Pj0, Uj0, acc[mt][nt][0], nscln2);
                oA.y = bias_elt(Pia, Uia, Pj1, Uj1, acc[mt][nt][1], nscln2);
                oB.x = bias_elt(Pib, Uib, Pj0, Uj0, acc[mt][nt][2], nscln2);
                oB.y = bias_elt(Pib, Uib, Pj1, Uj1, acc[mt][nt][3], nscln2);
                *(float2*)(out + rowA + j_c) = oA;
                *(float2*)(out + rowB + j_c) = oB;
                // transposed staging (STS banks 8*tq+g: conflict-free)
                stag[(j_c)     * PSTAG + i_a] = oA.x;
                stag[(j_c + 1) * PSTAG + i_a] = oA.y;
                stag[(j_c)     * PSTAG + i_b] = oB.x;
                stag[(j_c + 1) * PSTAG + i_b] = oB.y;
            }
        }
        // coalesced store of the transposed tile at (j0, i0)
        __syncthreads();
        size_t mbase = (size_t)b * S * S + (size_t)j0 * S + i0;
#pragma unroll
        for (int r2 = 0; r2 < 4; r2++) {
            int idx2 = r2 * 256 + t;            // 0..1023
            int j = idx2 >> 4, c2 = idx2 & 15;  // 64 rows x 16 float4-chunks
            float4 v = *(const float4*)(stag + j * PSTAG + 4 * c2);
            *(float4*)(out + mbase + (size_t)j * S + 4 * c2) = v;
        }
    } else {
#pragma unroll
        for (int mt = 0; mt < 2; mt++) {
            int i_a = wm * 32 + mt * 16 + g;
            int i_b = i_a + 8;
            float Pia = sPi[i_a], Uia = sUi[i_a];
            float Pib = sPi[i_b], Uib = sUi[i_b];
            size_t rowA = (size_t)b * S * S + (size_t)(i0 + i_a) * S + j0;
            size_t rowB = rowA + 8u * S;
#pragma unroll
            for (int nt = 0; nt < 2; nt++) {
                int j_c = wn * 16 + nt * 8 + 2 * tq;
                float Pj0 = sPj[j_c],     Uj0 = sUj[j_c];
                float Pj1 = sPj[j_c + 1], Uj1 = sUj[j_c + 1];
                float2 oA, oB;
                oA.x = bias_elt_d(Pia, Uia, Pj0, Uj0, acc[mt][nt][0], nscln2,
                                  i_a == j_c);
                oA.y = bias_elt_d(Pia, Uia, Pj1, Uj1, acc[mt][nt][1], nscln2,
                                  i_a == j_c + 1);
                oB.x = bias_elt_d(Pib, Uib, Pj0, Uj0, acc[mt][nt][2], nscln2,
                                  i_b == j_c);
                oB.y = bias_elt_d(Pib, Uib, Pj1, Uj1, acc[mt][nt][3], nscln2,
                                  i_b == j_c + 1);
                *(float2*)(out + rowA + j_c) = oA;
                *(float2*)(out + rowB + j_c) = oB;
            }
        }
    }
}

// ---------------------------------------------------------------------------
// Main: each CTA processes TWO 64x64 upper-triangle tiles; both tiles'
// cp.async staging is issued up-front so tile 1's load latency is fully
// hidden behind tile 0's compute. Launched with PDL after prep.
// ---------------------------------------------------------------------------
__global__ __launch_bounds__(256, 3)
void bias_kernel(const float* __restrict__ scale_p,
                 float* __restrict__ out, int S, int nwork) {
    extern __shared__ char sm[];
    uint32_t sb = smem_u32(sm);

    int ntile = S >> 6;
    int npairs = ntile * (ntile + 1) / 2;
    int t = threadIdx.x;
    int wid = t >> 5, lane = t & 31;

    int idx0 = blockIdx.x;
    int idx1 = blockIdx.x + gridDim.x;
    int b0, ti0, tj0, b1 = 0, ti1 = 0, tj1 = 0;
    decode_tile(idx0, ntile, npairs, b0, ti0, tj0);
    bool has1 = (idx1 < nwork);
    if (has1) decode_tile(idx1, ntile, npairs, b1, ti1, tj1);

    // ---- PDL: wait for prep's writes to be visible ----
    asm volatile("griddepcontrol.wait;" ::: "memory");

    // ---- issue both tiles' staging; groups: 0 = tile0, 1 = tile1 ----
    stage_tile(sb, 0, b0 * S, ti0 * 64, tj0 * 64, t);
    if (has1) stage_tile(sb, BUF, b1 * S, ti1 * 64, tj1 * 64, t);
    else cp_commit();                      // keep group accounting uniform

    float nscln2 = -scale_p[0] * 0.6931471805599453f;

    cp_wait<1>();                          // tile0 resident
    __syncthreads();
    process_tile(sm, sb, 0, b0, ti0, tj0, out, S, nscln2, t, wid, lane);

    if (has1) {
        cp_wait<0>();                      // tile1 resident (long since)
        __syncthreads();
        process_tile(sm, sb, BUF, b1, ti1, tj1, out, S, nscln2, t, wid, lane);
    }
}

// ---------------------------------------------------------------------------
extern "C" void kernel_launch(void* const* d_in, const int* in_sizes, int n_in,
                              void* d_out, int out_size) {
    const void*  ids     = d_in[0];
    const float* W       = (const float*)d_in[1];
    const float* scale_p = (const float*)d_in[2];
    float* out = (float*)d_out;

    int n_ids   = in_sizes[0];            // B*S = 4096
    int num_tok = in_sizes[1] / D;        // 30522
    int S       = out_size / n_ids;       // 1024
    int B       = n_ids / S;              // 4

    static int attr_set = 0;
    if (!attr_set) {
        cudaFuncSetAttribute(bias_kernel,
                             cudaFuncAttributeMaxDynamicSharedMemorySize,
                             SMEM_TOT);
        attr_set = 1;
    }

    int prep_blocks = (n_ids + 31) / 32;  // 32 tokens per 256-thread block
    prep_kernel<<<prep_blocks, 256>>>(ids, W, n_ids, num_tok);

    int ntile = S / 64;
    int pairs = ntile * (ntile + 1) / 2;  // 136 for S=1024
    int nwork = pairs * B;                // 544
    int nblk  = (nwork + 1) / 2;          // 272 CTAs, 2 tiles each

    // PDL launch: bias prologue overlaps prep; griddepcontrol.wait gates reads.
    cudaLaunchConfig_t cfg = {};
    cfg.gridDim = dim3(nblk, 1, 1);
    cfg.blockDim = dim3(256, 1, 1);
    cfg.dynamicSmemBytes = SMEM_TOT;
    cfg.stream = 0;
    cudaLaunchAttribute attrs[1];
    attrs[0].id = cudaLaunchAttributeProgrammaticStreamSerialization;
    attrs[0].val.programmaticStreamSerializationAllowed = 1;
    cfg.attrs = attrs;
    cfg.numAttrs = 1;
    cudaLaunchKernelEx(&cfg, bias_kernel, scale_p, out, S, nwork);
}